// round 13
// baseline (speedup 1.0000x reference)
#include <cuda_runtime.h>
#include <cuda_bf16.h>
#include <cstdint>
#include <math.h>

#define B     4
#define DIM   256
#define N     2048
#define HEADS 8
#define DH    64
#define HID   512
#define QK_SCALE 0.125f

typedef __nv_bfloat16 bf16;

// ---------------- scratch planes (device globals; no allocations) -----------
__device__ bf16 g_wqh[3 * HID * DIM], g_wql[3 * HID * DIM];   // [1536][256]
__device__ bf16 g_woh[DIM * HID],     g_wol[DIM * HID];       // [256][512]
__device__ bf16 g_xh[(size_t)B * N * DIM],  g_xl[(size_t)B * N * DIM];   // [b][t][k]
__device__ bf16 g_qh[(size_t)B * HEADS * N * DH], g_ql[(size_t)B * HEADS * N * DH]; // [b,h][t][d]
__device__ bf16 g_kh[(size_t)B * HEADS * N * DH], g_kl[(size_t)B * HEADS * N * DH]; // [b,h][t][d]
__device__ bf16 g_vh[(size_t)B * HEADS * DH * N], g_vl[(size_t)B * HEADS * DH * N]; // [b,h][d][t]
__device__ bf16 g_ah[(size_t)B * N * HID], g_al[(size_t)B * N * HID];    // [b][t][c]

// ============================ helpers =======================================
__device__ __forceinline__ uint32_t pack_bf16(float lo, float hi) {
    uint32_t r;
    asm("cvt.rn.bf16x2.f32 %0, %1, %2;" : "=r"(r) : "f"(hi), "f"(lo));
    return r;
}
__device__ __forceinline__ float bf16_round(float x) {
    return __bfloat162float(__float2bfloat16(x));
}
__device__ __forceinline__ uint32_t smem_u32(const void* p) {
    uint32_t a;
    asm("{ .reg .u64 t; cvta.to.shared.u64 t, %1; cvt.u32.u64 %0, t; }" : "=r"(a) : "l"(p));
    return a;
}

#define MMA_BF16_2(C, A, b0, b1)                                               \
    asm volatile(                                                              \
        "mma.sync.aligned.m16n8k16.row.col.f32.bf16.bf16.f32 "                 \
        "{%0,%1,%2,%3}, {%4,%5,%6,%7}, {%8,%9}, {%0,%1,%2,%3};"                \
        : "+f"((C)[0]), "+f"((C)[1]), "+f"((C)[2]), "+f"((C)[3])               \
        : "r"((A)[0]), "r"((A)[1]), "r"((A)[2]), "r"((A)[3]),                  \
          "r"(b0), "r"(b1))

#define LDSM_X4(R, a)                                                          \
    asm volatile("ldmatrix.sync.aligned.m8n8.x4.shared.b16 {%0,%1,%2,%3}, [%4];" \
        : "=r"((R)[0]), "=r"((R)[1]), "=r"((R)[2]), "=r"((R)[3]) : "r"(a))

#define RS 144   // smem row stride bytes (72 bf16): conflict-free ldmatrix

// ======================= split kernels (run once per launch) ================
__global__ __launch_bounds__(256) void split_w(const float* __restrict__ wq,
                                               const float* __restrict__ wo) {
    int i = blockIdx.x * 256 + threadIdx.x;
    const int NQ = 3 * HID * DIM;
    if (i < NQ) {
        float v = wq[i], hi = bf16_round(v);
        g_wqh[i] = __float2bfloat16(hi);
        g_wql[i] = __float2bfloat16(v - hi);
    } else {
        int j = i - NQ;
        float v = wo[j], hi = bf16_round(v);
        g_woh[j] = __float2bfloat16(hi);
        g_wol[j] = __float2bfloat16(v - hi);
    }
}

// x [b][k][t] fp32 -> g_xh/g_xl [b][t][k] bf16 (64x64 smem transpose tiles)
__global__ __launch_bounds__(256) void split_x(const float* __restrict__ x) {
    __shared__ float ts[64][65];
    const int t0 = blockIdx.x * 64, k0 = blockIdx.y * 64, b = blockIdx.z;
    const int tid = threadIdx.x;
    #pragma unroll
    for (int it = 0; it < 4; it++) {
        int idx = tid + it * 256;          // 1024 float4
        int kr = idx >> 4, t4 = idx & 15;
        float4 v = *(const float4*)&x[(size_t)b * DIM * N + (size_t)(k0 + kr) * N + t0 + t4 * 4];
        ts[kr][t4 * 4 + 0] = v.x; ts[kr][t4 * 4 + 1] = v.y;
        ts[kr][t4 * 4 + 2] = v.z; ts[kr][t4 * 4 + 3] = v.w;
    }
    __syncthreads();
    #pragma unroll
    for (int it = 0; it < 8; it++) {
        int idx = tid + it * 256;          // 2048 u32
        int tr = idx >> 5, kp = idx & 31;
        float e0 = ts[kp * 2][tr], e1 = ts[kp * 2 + 1][tr];
        float h0 = bf16_round(e0), h1 = bf16_round(e1);
        size_t a = (size_t)b * N * DIM + (size_t)(t0 + tr) * DIM + k0 + kp * 2;
        *(uint32_t*)&g_xh[a] = pack_bf16(h0, h1);
        *(uint32_t*)&g_xl[a] = pack_bf16(e0 - h0, e1 - h1);
    }
}

// ================ GEMM: dst[o,t] = sum_k w[o,k] src[t,k]  (bf16 3-term) =====
// CTA 128o x 64t, 128 threads / 4 warps; warp owns 32 o rows (2 m16 tiles).
// smem: wH 0 (128xRS), wL 18432, xH 36864 (64xRS), xL 46080. Total 55296.
#define SM_GEMM 55296

template<int KTOT, int EPI>
__global__ __launch_bounds__(128, 2) void gemm_kernel(
        const float* __restrict__ bias, float* __restrict__ dst) {
    extern __shared__ char smem[];
    const int tid = threadIdx.x;
    const int wid = tid >> 5, lane = tid & 31;
    const int qr = lane >> 2, qc = lane & 3;
    const int t0 = blockIdx.x * 64, o0 = blockIdx.y * 128, b = blockIdx.z;

    const bf16* wh = (EPI == 0) ? g_wqh : g_woh;
    const bf16* wl = (EPI == 0) ? g_wql : g_wol;
    const bf16* xh = (EPI == 0) ? g_xh  : g_ah;
    const bf16* xl = (EPI == 0) ? g_xl  : g_al;

    const uint32_t sb = smem_u32(smem);
    const uint32_t aOff = (uint32_t)((lane & 15) * RS + (lane >> 4) * 16);
    const uint32_t bOff = (uint32_t)((lane >> 4) * 9216 + ((lane >> 3) & 1) * 16 + (lane & 7) * RS);
    const uint32_t wA = sb + (uint32_t)(wid * 32) * RS + aOff;
    const uint32_t xB = sb + 36864u + bOff;

    const bf16* xhb = xh + (size_t)b * N * KTOT;
    const bf16* xlb = xl + (size_t)b * N * KTOT;
    float C[2][8][4] = {};

    for (int k0 = 0; k0 < KTOT; k0 += 64) {
        __syncthreads();
        #pragma unroll
        for (int it = 0; it < 8; it++) {
            int idx = tid + it * 128;               // 1024: w rows
            int row = idx >> 3, ch = idx & 7;
            uint32_t so = (uint32_t)row * RS + ch * 16;
            *(uint4*)(smem + so) =
                *(const uint4*)(wh + (size_t)(o0 + row) * KTOT + k0 + ch * 8);
            *(uint4*)(smem + 18432 + so) =
                *(const uint4*)(wl + (size_t)(o0 + row) * KTOT + k0 + ch * 8);
        }
        #pragma unroll
        for (int it = 0; it < 4; it++) {
            int idx = tid + it * 128;               // 512: x rows
            int row = idx >> 3, ch = idx & 7;
            uint32_t so = (uint32_t)row * RS + ch * 16;
            *(uint4*)(smem + 36864 + so) =
                *(const uint4*)(xhb + (size_t)(t0 + row) * KTOT + k0 + ch * 8);
            *(uint4*)(smem + 46080 + so) =
                *(const uint4*)(xlb + (size_t)(t0 + row) * KTOT + k0 + ch * 8);
        }
        __syncthreads();

        uint32_t awh[2][4][4], awl[2][4][4];
        #pragma unroll
        for (int m = 0; m < 2; m++)
            #pragma unroll
            for (int ks = 0; ks < 4; ks++) {
                LDSM_X4(awh[m][ks], wA + (uint32_t)m * (16 * RS) + ks * 32);
                LDSM_X4(awl[m][ks], wA + 18432u + (uint32_t)m * (16 * RS) + ks * 32);
            }
        #pragma unroll
        for (int np = 0; np < 4; np++) {
            const int n0 = np * 2, n1 = np * 2 + 1;
            uint32_t bx0[4][4], bx1[4][4];
            #pragma unroll
            for (int ks = 0; ks < 4; ks++) {
                LDSM_X4(bx0[ks], xB + (uint32_t)n0 * (8 * RS) + ks * 32);
                LDSM_X4(bx1[ks], xB + (uint32_t)n1 * (8 * RS) + ks * 32);
            }
            #pragma unroll
            for (int ks = 0; ks < 4; ks++) {
                MMA_BF16_2(C[0][n0], awh[0][ks], bx0[ks][0], bx0[ks][1]);
                MMA_BF16_2(C[1][n0], awh[1][ks], bx0[ks][0], bx0[ks][1]);
                MMA_BF16_2(C[0][n1], awh[0][ks], bx1[ks][0], bx1[ks][1]);
                MMA_BF16_2(C[1][n1], awh[1][ks], bx1[ks][0], bx1[ks][1]);
                MMA_BF16_2(C[0][n0], awh[0][ks], bx0[ks][2], bx0[ks][3]);
                MMA_BF16_2(C[1][n0], awh[1][ks], bx0[ks][2], bx0[ks][3]);
                MMA_BF16_2(C[0][n1], awh[0][ks], bx1[ks][2], bx1[ks][3]);
                MMA_BF16_2(C[1][n1], awh[1][ks], bx1[ks][2], bx1[ks][3]);
                MMA_BF16_2(C[0][n0], awl[0][ks], bx0[ks][0], bx0[ks][1]);
                MMA_BF16_2(C[1][n0], awl[1][ks], bx0[ks][0], bx0[ks][1]);
                MMA_BF16_2(C[0][n1], awl[0][ks], bx1[ks][0], bx1[ks][1]);
                MMA_BF16_2(C[1][n1], awl[1][ks], bx1[ks][0], bx1[ks][1]);
            }
        }
    }

    if (EPI == 1) {
        float* db = dst + (size_t)b * DIM * N;
        #pragma unroll
        for (int m = 0; m < 2; m++) {
            const int r0 = o0 + wid * 32 + m * 16 + qr;
            float b0 = bias[r0], b1 = bias[r0 + 8];
            #pragma unroll
            for (int nt = 0; nt < 8; nt++) {
                const int t = t0 + nt * 8 + qc * 2;
                *(float2*)&db[(size_t)r0 * N + t] =
                    make_float2(C[m][nt][0] + b0, C[m][nt][1] + b0);
                *(float2*)&db[(size_t)(r0 + 8) * N + t] =
                    make_float2(C[m][nt][2] + b1, C[m][nt][3] + b1);
            }
        }
    } else {
        const int type = o0 >> 9;                          // 0:q 1:k 2:v
        #pragma unroll
        for (int m = 0; m < 2; m++) {
            const int oo = (o0 & 511) + wid * 32 + m * 16;
            const int hh = oo >> 6;                        // uniform per warp-half
            const int d0 = (oo & 63) + qr;
            const size_t bh = (size_t)b * HEADS + hh;
            if (type == 2) {
                #pragma unroll
                for (int nt = 0; nt < 8; nt++) {
                    const int t = t0 + nt * 8 + qc * 2;
                    float h0 = bf16_round(C[m][nt][0]), h1 = bf16_round(C[m][nt][1]);
                    float h2 = bf16_round(C[m][nt][2]), h3 = bf16_round(C[m][nt][3]);
                    size_t a0 = (bh * DH + d0) * N + t;
                    size_t a1 = (bh * DH + d0 + 8) * N + t;
                    *(uint32_t*)&g_vh[a0] = pack_bf16(h0, h1);
                    *(uint32_t*)&g_vl[a0] = pack_bf16(C[m][nt][0] - h0, C[m][nt][1] - h1);
                    *(uint32_t*)&g_vh[a1] = pack_bf16(h2, h3);
                    *(uint32_t*)&g_vl[a1] = pack_bf16(C[m][nt][2] - h2, C[m][nt][3] - h3);
                }
            } else {
                bf16* ph = (type == 0) ? g_qh : g_kh;
                bf16* pl = (type == 0) ? g_ql : g_kl;
                const float s = (type == 0) ? QK_SCALE : 1.f;
                #pragma unroll
                for (int nt = 0; nt < 8; nt++) {
                    const int t = t0 + nt * 8 + qc * 2;
                    float v0 = C[m][nt][0] * s, v1 = C[m][nt][1] * s;
                    float v2 = C[m][nt][2] * s, v3 = C[m][nt][3] * s;
                    float h0 = bf16_round(v0), h1 = bf16_round(v1);
                    float h2 = bf16_round(v2), h3 = bf16_round(v3);
                    size_t a = (bh * N + t) * DH + d0;
                    ph[a]          = __float2bfloat16(h0); pl[a]          = __float2bfloat16(v0 - h0);
                    ph[a + DH]     = __float2bfloat16(h1); pl[a + DH]     = __float2bfloat16(v1 - h1);
                    ph[a + 8]      = __float2bfloat16(h2); pl[a + 8]      = __float2bfloat16(v2 - h2);
                    ph[a + DH + 8] = __float2bfloat16(h3); pl[a + DH + 8] = __float2bfloat16(v3 - h3);
                }
            }
        }
    }
}

// ======== attention: Q in SMEM (regs freed), pr-pipelined, spill-free =======
// CTA: 128 q x (b,h). 128 threads / 4 warps, 32 q/warp. 64-key tiles.
// smem: Q @0 {qh 0, ql 18432} persistent; buf(i) @36864+i*36864:
//       {kh 0, kl 9216, vh 18432, vl 27648}. Total 110592 (2 CTAs = 216KB).
#define SM_ATTN 110592

__device__ __forceinline__ void qk_burst(float (&S)[2][2][4], uint32_t kbase,
                                         uint32_t qbase) {
    #pragma unroll
    for (int m = 0; m < 2; m++)
        #pragma unroll
        for (int nn = 0; nn < 2; nn++)
            #pragma unroll
            for (int i = 0; i < 4; i++) S[m][nn][i] = 0.f;
    #pragma unroll
    for (int ks = 0; ks < 4; ks++) {
        uint32_t bk0[4], bk1[4], qh0[4], qh1[4], ql0[4], ql1[4];
        LDSM_X4(bk0, kbase + ks * 32);
        LDSM_X4(bk1, kbase + (uint32_t)(8 * RS) + ks * 32);
        LDSM_X4(qh0, qbase + ks * 32);
        LDSM_X4(qh1, qbase + (uint32_t)(16 * RS) + ks * 32);
        LDSM_X4(ql0, qbase + 18432u + ks * 32);
        LDSM_X4(ql1, qbase + 18432u + (uint32_t)(16 * RS) + ks * 32);
        MMA_BF16_2(S[0][0], qh0, bk0[0], bk0[1]);
        MMA_BF16_2(S[1][0], qh1, bk0[0], bk0[1]);
        MMA_BF16_2(S[0][1], qh0, bk1[0], bk1[1]);
        MMA_BF16_2(S[1][1], qh1, bk1[0], bk1[1]);
        MMA_BF16_2(S[0][0], qh0, bk0[2], bk0[3]);
        MMA_BF16_2(S[1][0], qh1, bk0[2], bk0[3]);
        MMA_BF16_2(S[0][1], qh0, bk1[2], bk1[3]);
        MMA_BF16_2(S[1][1], qh1, bk1[2], bk1[3]);
        MMA_BF16_2(S[0][0], ql0, bk0[0], bk0[1]);
        MMA_BF16_2(S[1][0], ql1, bk0[0], bk0[1]);
        MMA_BF16_2(S[0][1], ql0, bk1[0], bk1[1]);
        MMA_BF16_2(S[1][1], ql1, bk1[0], bk1[1]);
    }
}

__global__ __launch_bounds__(128, 2) void attn_kernel() {
    extern __shared__ char smem[];
    const int tid = threadIdx.x;
    const int wid = tid >> 5, lane = tid & 31;
    const int qr = lane >> 2, qc = lane & 3;
    const int i0 = blockIdx.x * 128, h = blockIdx.y, b = blockIdx.z;
    const size_t bh = (size_t)b * HEADS + h;

    const uint32_t sb = smem_u32(smem);
    const uint32_t aOff = (uint32_t)((lane & 15) * RS + (lane >> 4) * 16);
    const uint32_t bOff = (uint32_t)((lane >> 4) * 9216 + ((lane >> 3) & 1) * 16 + (lane & 7) * RS);
    const uint32_t qBase = sb + (uint32_t)(wid * 32) * RS + aOff;

    const bf16* khp = g_kh + bh * N * DH;
    const bf16* klp = g_kl + bh * N * DH;
    const bf16* vhp = g_vh + bh * DH * N;
    const bf16* vlp = g_vl + bh * DH * N;

    // ---- stage Q planes into persistent smem region (never overwritten) ----
    const bf16* qhp = g_qh + (bh * N + i0) * DH;
    const bf16* qlp = g_ql + (bh * N + i0) * DH;
    #pragma unroll
    for (int it = 0; it < 8; it++) {
        int idx = tid + it * 128;          // 1024 uint4 per plane
        int row = idx >> 3, ch = idx & 7;
        uint32_t so = (uint32_t)row * RS + ch * 16;
        *(uint4*)(smem + so)         = *(const uint4*)(qhp + (size_t)row * DH + ch * 8);
        *(uint4*)(smem + 18432 + so) = *(const uint4*)(qlp + (size_t)row * DH + ch * 8);
    }

    float O[2][8][4] = {};
    float ls0[2] = {0.f, 0.f}, ls1[2] = {0.f, 0.f};

    for (int tile = 0; tile < 32; tile++) {
        const int j0 = tile * 64;
        char* bb = smem + 36864 + (tile & 1) * 36864;
        // fill current K/V buffer (1-sync/tile protocol: safe, see R11)
        #pragma unroll
        for (int it = 0; it < 4; it++) {
            int idx = tid + it * 128;      // 512 uint4 per plane
            int row = idx >> 3, ch = idx & 7;
            uint32_t so = (uint32_t)row * RS + ch * 16;
            *(uint4*)(bb + so)         = *(const uint4*)(khp + (size_t)(j0 + row) * DH + ch * 8);
            *(uint4*)(bb + 9216 + so)  = *(const uint4*)(klp + (size_t)(j0 + row) * DH + ch * 8);
            *(uint4*)(bb + 18432 + so) = *(const uint4*)(vhp + (size_t)row * N + j0 + ch * 8);
            *(uint4*)(bb + 27648 + so) = *(const uint4*)(vlp + (size_t)row * N + j0 + ch * 8);
        }
        __syncthreads();   // also covers Q staging on tile 0

        const uint32_t kB = sb + 36864u + (uint32_t)((tile & 1) * 36864) + bOff;
        const uint32_t vB = kB + 18432u;

        float S[2][2][2][4];   // [parity][m][nn][4]
        qk_burst(S[0], kB, qBase);

        #pragma unroll
        for (int pr = 0; pr < 4; pr++) {
            const int cur = pr & 1;
            // issue next QK burst first -> tensor busy during softmax below
            if (pr < 3)
                qk_burst(S[cur ^ 1], kB + (uint32_t)((pr + 1) * 16) * RS, qBase);

            // softmax(pr): max-free exp + pack P fragments
            uint32_t pah[2][4], pal[2][4];
            #pragma unroll
            for (int m = 0; m < 2; m++)
                #pragma unroll
                for (int nn = 0; nn < 2; nn++) {
                    float p0 = __expf(S[cur][m][nn][0]), p1 = __expf(S[cur][m][nn][1]);
                    float p2 = __expf(S[cur][m][nn][2]), p3 = __expf(S[cur][m][nn][3]);
                    ls0[m] += p0 + p1;
                    ls1[m] += p2 + p3;
                    float h0 = bf16_round(p0), h1 = bf16_round(p1);
                    float h2 = bf16_round(p2), h3 = bf16_round(p3);
                    pah[m][nn * 2 + 0] = pack_bf16(p0, p1);
                    pah[m][nn * 2 + 1] = pack_bf16(p2, p3);
                    pal[m][nn * 2 + 0] = pack_bf16(p0 - h0, p1 - h1);
                    pal[m][nn * 2 + 1] = pack_bf16(p2 - h2, p3 - h3);
                }
            // PV(pr): interleaved chains O[m][nd]
            #pragma unroll
            for (int ndp = 0; ndp < 4; ndp++) {
                const int n0 = ndp * 2, n1 = ndp * 2 + 1;
                uint32_t bv0[4], bv1[4];
                LDSM_X4(bv0, vB + (uint32_t)n0 * (8 * RS) + pr * 32);
                LDSM_X4(bv1, vB + (uint32_t)n1 * (8 * RS) + pr * 32);
                MMA_BF16_2(O[0][n0], pah[0], bv0[0], bv0[1]);
                MMA_BF16_2(O[1][n0], pah[1], bv0[0], bv0[1]);
                MMA_BF16_2(O[0][n1], pah[0], bv1[0], bv1[1]);
                MMA_BF16_2(O[1][n1], pah[1], bv1[0], bv1[1]);
                MMA_BF16_2(O[0][n0], pah[0], bv0[2], bv0[3]);
                MMA_BF16_2(O[1][n0], pah[1], bv0[2], bv0[3]);
                MMA_BF16_2(O[0][n1], pah[0], bv1[2], bv1[3]);
                MMA_BF16_2(O[1][n1], pah[1], bv1[2], bv1[3]);
                MMA_BF16_2(O[0][n0], pal[0], bv0[0], bv0[1]);
                MMA_BF16_2(O[1][n0], pal[1], bv0[0], bv0[1]);
                MMA_BF16_2(O[0][n1], pal[0], bv1[0], bv1[1]);
                MMA_BF16_2(O[1][n1], pal[1], bv1[0], bv1[1]);
            }
        }
    }

    #pragma unroll
    for (int m = 0; m < 2; m++) {
        ls0[m] += __shfl_xor_sync(0xffffffffu, ls0[m], 1);
        ls0[m] += __shfl_xor_sync(0xffffffffu, ls0[m], 2);
        ls1[m] += __shfl_xor_sync(0xffffffffu, ls1[m], 1);
        ls1[m] += __shfl_xor_sync(0xffffffffu, ls1[m], 2);
    }

    // ---- epilogue: normalized bf16 hi/lo -> g_ah/g_al [b][t][c] ----
    #pragma unroll
    for (int m = 0; m < 2; m++) {
        const float inv0 = 1.f / ls0[m], inv1 = 1.f / ls1[m];
        size_t r0 = ((size_t)b * N + i0 + wid * 32 + m * 16 + qr) * HID + h * DH;
        size_t r1 = r0 + 8 * HID;
        #pragma unroll
        for (int nd = 0; nd < 8; nd++) {
            const int d = nd * 8 + qc * 2;
            float v0 = O[m][nd][0] * inv0, v1 = O[m][nd][1] * inv0;
            float v2 = O[m][nd][2] * inv1, v3 = O[m][nd][3] * inv1;
            float h0 = bf16_round(v0), h1 = bf16_round(v1);
            float h2 = bf16_round(v2), h3 = bf16_round(v3);
            *(uint32_t*)&g_ah[r0 + d] = pack_bf16(h0, h1);
            *(uint32_t*)&g_al[r0 + d] = pack_bf16(v0 - h0, v1 - h1);
            *(uint32_t*)&g_ah[r1 + d] = pack_bf16(h2, h3);
            *(uint32_t*)&g_al[r1 + d] = pack_bf16(v2 - h2, v3 - h3);
        }
    }
}

// ---------------------------------------------------------------------------
extern "C" void kernel_launch(void* const* d_in, const int* in_sizes, int n_in,
                              void* d_out, int out_size) {
    const float* x     = (const float*)d_in[0];
    const float* w_qkv = (const float*)d_in[1];
    const float* w_out = (const float*)d_in[2];
    const float* b_out = (const float*)d_in[3];
    float* out = (float*)d_out;

    cudaFuncSetAttribute(gemm_kernel<DIM, 0>,
                         cudaFuncAttributeMaxDynamicSharedMemorySize, SM_GEMM);
    cudaFuncSetAttribute(gemm_kernel<HID, 1>,
                         cudaFuncAttributeMaxDynamicSharedMemorySize, SM_GEMM);
    cudaFuncSetAttribute(attn_kernel,
                         cudaFuncAttributeMaxDynamicSharedMemorySize, SM_ATTN);

    split_w<<<(3 * HID * DIM + DIM * HID) / 256, 256>>>(w_qkv, w_out);
    split_x<<<dim3(N / 64, DIM / 64, B), 256>>>(x);
    gemm_kernel<DIM, 0><<<dim3(N / 64, 3 * HID / 128, B), 128, SM_GEMM>>>(nullptr, nullptr);
    attn_kernel<<<dim3(N / 128, HEADS, B), 128, SM_ATTN>>>();
    gemm_kernel<HID, 1><<<dim3(N / 64, DIM / 128, B), 128, SM_GEMM>>>(b_out, out);
}

// round 14
// speedup vs baseline: 1.2887x; 1.2887x over previous
#include <cuda_runtime.h>
#include <cuda_bf16.h>
#include <cuda_fp16.h>
#include <cstdint>
#include <math.h>

#define B     4
#define DIM   256
#define N     2048
#define HEADS 8
#define DH    64
#define HID   512
#define QK_SCALE 0.125f

typedef __nv_bfloat16 bf16;

// ---------------- scratch planes (device globals; no allocations) -----------
__device__ bf16 g_wqh[3 * HID * DIM], g_wql[3 * HID * DIM];   // [1536][256]
__device__ bf16 g_woh[DIM * HID],     g_wol[DIM * HID];       // [256][512]
__device__ bf16 g_xh[(size_t)B * N * DIM],  g_xl[(size_t)B * N * DIM];   // [b][t][k]
// attention operands: fp16 (q single plane, k/v hi+lo)
__device__ __half g_qf[(size_t)B * HEADS * N * DH];                       // [b,h][t][d]
__device__ __half g_kh[(size_t)B * HEADS * N * DH], g_kl[(size_t)B * HEADS * N * DH];
__device__ __half g_vh[(size_t)B * HEADS * DH * N], g_vl[(size_t)B * HEADS * DH * N];
__device__ bf16 g_ah[(size_t)B * N * HID], g_al[(size_t)B * N * HID];    // [b][t][c]

// ============================ helpers =======================================
__device__ __forceinline__ uint32_t pack_bf16(float lo, float hi) {
    uint32_t r;
    asm("cvt.rn.bf16x2.f32 %0, %1, %2;" : "=r"(r) : "f"(hi), "f"(lo));
    return r;
}
__device__ __forceinline__ float bf16_round(float x) {
    return __bfloat162float(__float2bfloat16(x));
}
__device__ __forceinline__ uint32_t pack_f16(float lo, float hi) {
    __half2 h = __floats2half2_rn(lo, hi);   // lo -> low half
    return *(uint32_t*)&h;
}
__device__ __forceinline__ uint32_t smem_u32(const void* p) {
    uint32_t a;
    asm("{ .reg .u64 t; cvta.to.shared.u64 t, %1; cvt.u32.u64 %0, t; }" : "=r"(a) : "l"(p));
    return a;
}

#define MMA_BF16_2(C, A, b0, b1)                                               \
    asm volatile(                                                              \
        "mma.sync.aligned.m16n8k16.row.col.f32.bf16.bf16.f32 "                 \
        "{%0,%1,%2,%3}, {%4,%5,%6,%7}, {%8,%9}, {%0,%1,%2,%3};"                \
        : "+f"((C)[0]), "+f"((C)[1]), "+f"((C)[2]), "+f"((C)[3])               \
        : "r"((A)[0]), "r"((A)[1]), "r"((A)[2]), "r"((A)[3]),                  \
          "r"(b0), "r"(b1))

#define MMA_F16_2(C, A, b0, b1)                                                \
    asm volatile(                                                              \
        "mma.sync.aligned.m16n8k16.row.col.f32.f16.f16.f32 "                   \
        "{%0,%1,%2,%3}, {%4,%5,%6,%7}, {%8,%9}, {%0,%1,%2,%3};"                \
        : "+f"((C)[0]), "+f"((C)[1]), "+f"((C)[2]), "+f"((C)[3])               \
        : "r"((A)[0]), "r"((A)[1]), "r"((A)[2]), "r"((A)[3]),                  \
          "r"(b0), "r"(b1))

#define LDSM_X4(R, a)                                                          \
    asm volatile("ldmatrix.sync.aligned.m8n8.x4.shared.b16 {%0,%1,%2,%3}, [%4];" \
        : "=r"((R)[0]), "=r"((R)[1]), "=r"((R)[2]), "=r"((R)[3]) : "r"(a))

#define RS 144   // smem row stride bytes (72 elems): conflict-free ldmatrix

// ======================= split kernels (run once per launch) ================
__global__ __launch_bounds__(256) void split_w(const float* __restrict__ wq,
                                               const float* __restrict__ wo) {
    int i = blockIdx.x * 256 + threadIdx.x;
    const int NQ = 3 * HID * DIM;
    if (i < NQ) {
        float v = wq[i], hi = bf16_round(v);
        g_wqh[i] = __float2bfloat16(hi);
        g_wql[i] = __float2bfloat16(v - hi);
    } else {
        int j = i - NQ;
        float v = wo[j], hi = bf16_round(v);
        g_woh[j] = __float2bfloat16(hi);
        g_wol[j] = __float2bfloat16(v - hi);
    }
}

// x [b][k][t] fp32 -> g_xh/g_xl [b][t][k] bf16 (64x64 smem transpose tiles)
__global__ __launch_bounds__(256) void split_x(const float* __restrict__ x) {
    __shared__ float ts[64][65];
    const int t0 = blockIdx.x * 64, k0 = blockIdx.y * 64, b = blockIdx.z;
    const int tid = threadIdx.x;
    #pragma unroll
    for (int it = 0; it < 4; it++) {
        int idx = tid + it * 256;
        int kr = idx >> 4, t4 = idx & 15;
        float4 v = *(const float4*)&x[(size_t)b * DIM * N + (size_t)(k0 + kr) * N + t0 + t4 * 4];
        ts[kr][t4 * 4 + 0] = v.x; ts[kr][t4 * 4 + 1] = v.y;
        ts[kr][t4 * 4 + 2] = v.z; ts[kr][t4 * 4 + 3] = v.w;
    }
    __syncthreads();
    #pragma unroll
    for (int it = 0; it < 8; it++) {
        int idx = tid + it * 256;
        int tr = idx >> 5, kp = idx & 31;
        float e0 = ts[kp * 2][tr], e1 = ts[kp * 2 + 1][tr];
        float h0 = bf16_round(e0), h1 = bf16_round(e1);
        size_t a = (size_t)b * N * DIM + (size_t)(t0 + tr) * DIM + k0 + kp * 2;
        *(uint32_t*)&g_xh[a] = pack_bf16(h0, h1);
        *(uint32_t*)&g_xl[a] = pack_bf16(e0 - h0, e1 - h1);
    }
}

// ================ GEMM: dst[o,t] = sum_k w[o,k] src[t,k]  (bf16 3-term) =====
// CTA 128o x 64t, 128 threads / 4 warps; warp owns 32 o rows (2 m16 tiles).
#define SM_GEMM 55296

template<int KTOT, int EPI>
__global__ __launch_bounds__(128, 2) void gemm_kernel(
        const float* __restrict__ bias, float* __restrict__ dst) {
    extern __shared__ char smem[];
    const int tid = threadIdx.x;
    const int wid = tid >> 5, lane = tid & 31;
    const int qr = lane >> 2, qc = lane & 3;
    const int t0 = blockIdx.x * 64, o0 = blockIdx.y * 128, b = blockIdx.z;

    const bf16* wh = (EPI == 0) ? g_wqh : g_woh;
    const bf16* wl = (EPI == 0) ? g_wql : g_wol;
    const bf16* xh = (EPI == 0) ? g_xh  : g_ah;
    const bf16* xl = (EPI == 0) ? g_xl  : g_al;

    const uint32_t sb = smem_u32(smem);
    const uint32_t aOff = (uint32_t)((lane & 15) * RS + (lane >> 4) * 16);
    const uint32_t bOff = (uint32_t)((lane >> 4) * 9216 + ((lane >> 3) & 1) * 16 + (lane & 7) * RS);
    const uint32_t wA = sb + (uint32_t)(wid * 32) * RS + aOff;
    const uint32_t xB = sb + 36864u + bOff;

    const bf16* xhb = xh + (size_t)b * N * KTOT;
    const bf16* xlb = xl + (size_t)b * N * KTOT;
    float C[2][8][4] = {};

    for (int k0 = 0; k0 < KTOT; k0 += 64) {
        __syncthreads();
        #pragma unroll
        for (int it = 0; it < 8; it++) {
            int idx = tid + it * 128;
            int row = idx >> 3, ch = idx & 7;
            uint32_t so = (uint32_t)row * RS + ch * 16;
            *(uint4*)(smem + so) =
                *(const uint4*)(wh + (size_t)(o0 + row) * KTOT + k0 + ch * 8);
            *(uint4*)(smem + 18432 + so) =
                *(const uint4*)(wl + (size_t)(o0 + row) * KTOT + k0 + ch * 8);
        }
        #pragma unroll
        for (int it = 0; it < 4; it++) {
            int idx = tid + it * 128;
            int row = idx >> 3, ch = idx & 7;
            uint32_t so = (uint32_t)row * RS + ch * 16;
            *(uint4*)(smem + 36864 + so) =
                *(const uint4*)(xhb + (size_t)(t0 + row) * KTOT + k0 + ch * 8);
            *(uint4*)(smem + 46080 + so) =
                *(const uint4*)(xlb + (size_t)(t0 + row) * KTOT + k0 + ch * 8);
        }
        __syncthreads();

        uint32_t awh[2][4][4], awl[2][4][4];
        #pragma unroll
        for (int m = 0; m < 2; m++)
            #pragma unroll
            for (int ks = 0; ks < 4; ks++) {
                LDSM_X4(awh[m][ks], wA + (uint32_t)m * (16 * RS) + ks * 32);
                LDSM_X4(awl[m][ks], wA + 18432u + (uint32_t)m * (16 * RS) + ks * 32);
            }
        #pragma unroll
        for (int np = 0; np < 4; np++) {
            const int n0 = np * 2, n1 = np * 2 + 1;
            uint32_t bx0[4][4], bx1[4][4];
            #pragma unroll
            for (int ks = 0; ks < 4; ks++) {
                LDSM_X4(bx0[ks], xB + (uint32_t)n0 * (8 * RS) + ks * 32);
                LDSM_X4(bx1[ks], xB + (uint32_t)n1 * (8 * RS) + ks * 32);
            }
            #pragma unroll
            for (int ks = 0; ks < 4; ks++) {
                MMA_BF16_2(C[0][n0], awh[0][ks], bx0[ks][0], bx0[ks][1]);
                MMA_BF16_2(C[1][n0], awh[1][ks], bx0[ks][0], bx0[ks][1]);
                MMA_BF16_2(C[0][n1], awh[0][ks], bx1[ks][0], bx1[ks][1]);
                MMA_BF16_2(C[1][n1], awh[1][ks], bx1[ks][0], bx1[ks][1]);
                MMA_BF16_2(C[0][n0], awh[0][ks], bx0[ks][2], bx0[ks][3]);
                MMA_BF16_2(C[1][n0], awh[1][ks], bx0[ks][2], bx0[ks][3]);
                MMA_BF16_2(C[0][n1], awh[0][ks], bx1[ks][2], bx1[ks][3]);
                MMA_BF16_2(C[1][n1], awh[1][ks], bx1[ks][2], bx1[ks][3]);
                MMA_BF16_2(C[0][n0], awl[0][ks], bx0[ks][0], bx0[ks][1]);
                MMA_BF16_2(C[1][n0], awl[1][ks], bx0[ks][0], bx0[ks][1]);
                MMA_BF16_2(C[0][n1], awl[0][ks], bx1[ks][0], bx1[ks][1]);
                MMA_BF16_2(C[1][n1], awl[1][ks], bx1[ks][0], bx1[ks][1]);
            }
        }
    }

    if (EPI == 1) {
        float* db = dst + (size_t)b * DIM * N;
        #pragma unroll
        for (int m = 0; m < 2; m++) {
            const int r0 = o0 + wid * 32 + m * 16 + qr;
            float b0 = bias[r0], b1 = bias[r0 + 8];
            #pragma unroll
            for (int nt = 0; nt < 8; nt++) {
                const int t = t0 + nt * 8 + qc * 2;
                *(float2*)&db[(size_t)r0 * N + t] =
                    make_float2(C[m][nt][0] + b0, C[m][nt][1] + b0);
                *(float2*)&db[(size_t)(r0 + 8) * N + t] =
                    make_float2(C[m][nt][2] + b1, C[m][nt][3] + b1);
            }
        }
    } else {
        const int type = o0 >> 9;                          // 0:q 1:k 2:v
        #pragma unroll
        for (int m = 0; m < 2; m++) {
            const int oo = (o0 & 511) + wid * 32 + m * 16;
            const int hh = oo >> 6;                        // uniform per warp-half
            const int d0 = (oo & 63) + qr;
            const size_t bh = (size_t)b * HEADS + hh;
            if (type == 0) {
                // q: single fp16 plane, pre-scaled
                #pragma unroll
                for (int nt = 0; nt < 8; nt++) {
                    const int t = t0 + nt * 8 + qc * 2;
                    size_t a = (bh * N + t) * DH + d0;
                    g_qf[a]          = __float2half(C[m][nt][0] * QK_SCALE);
                    g_qf[a + DH]     = __float2half(C[m][nt][1] * QK_SCALE);
                    g_qf[a + 8]      = __float2half(C[m][nt][2] * QK_SCALE);
                    g_qf[a + DH + 8] = __float2half(C[m][nt][3] * QK_SCALE);
                }
            } else if (type == 1) {
                // k: fp16 hi + lo planes
                #pragma unroll
                for (int nt = 0; nt < 8; nt++) {
                    const int t = t0 + nt * 8 + qc * 2;
                    size_t a = (bh * N + t) * DH + d0;
                    float v0 = C[m][nt][0], v1 = C[m][nt][1];
                    float v2 = C[m][nt][2], v3 = C[m][nt][3];
                    __half h0 = __float2half(v0), h1 = __float2half(v1);
                    __half h2 = __float2half(v2), h3 = __float2half(v3);
                    g_kh[a]          = h0; g_kl[a]          = __float2half(v0 - __half2float(h0));
                    g_kh[a + DH]     = h1; g_kl[a + DH]     = __float2half(v1 - __half2float(h1));
                    g_kh[a + 8]      = h2; g_kl[a + 8]      = __float2half(v2 - __half2float(h2));
                    g_kh[a + DH + 8] = h3; g_kl[a + DH + 8] = __float2half(v3 - __half2float(h3));
                }
            } else {
                // v: fp16 hi + lo planes, [d][t]
                #pragma unroll
                for (int nt = 0; nt < 8; nt++) {
                    const int t = t0 + nt * 8 + qc * 2;
                    float v0 = C[m][nt][0], v1 = C[m][nt][1];
                    float v2 = C[m][nt][2], v3 = C[m][nt][3];
                    float h0 = __half2float(__float2half(v0)), h1 = __half2float(__float2half(v1));
                    float h2 = __half2float(__float2half(v2)), h3 = __half2float(__float2half(v3));
                    size_t a0 = (bh * DH + d0) * N + t;
                    size_t a1 = (bh * DH + d0 + 8) * N + t;
                    *(uint32_t*)&g_vh[a0] = pack_f16(h0, h1);
                    *(uint32_t*)&g_vl[a0] = pack_f16(v0 - h0, v1 - h1);
                    *(uint32_t*)&g_vh[a1] = pack_f16(h2, h3);
                    *(uint32_t*)&g_vl[a1] = pack_f16(v2 - h2, v3 - h3);
                }
            }
        }
    }
}

// ====== attention: fp16 2-term (q,p single-plane; k,v hi/lo), pipelined =====
// CTA: 128 q x (b,h). 128 threads / 4 warps, 32 q/warp. 64-key tiles.
// smem: Q @0 (18432, persistent); buf(i) @18432+i*36864:
//       {kh 0, kl 9216, vh 18432, vl 27648}. Total 92160 (2 CTAs = 180KB).
#define SM_ATTN 92160

__device__ __forceinline__ void qk_burst(float (&S)[2][2][4], uint32_t kbase,
                                         uint32_t qbase) {
    #pragma unroll
    for (int m = 0; m < 2; m++)
        #pragma unroll
        for (int nn = 0; nn < 2; nn++)
            #pragma unroll
            for (int i = 0; i < 4; i++) S[m][nn][i] = 0.f;
    #pragma unroll
    for (int ks = 0; ks < 4; ks++) {
        uint32_t bk0[4], bk1[4], qh0[4], qh1[4];
        LDSM_X4(bk0, kbase + ks * 32);
        LDSM_X4(bk1, kbase + (uint32_t)(8 * RS) + ks * 32);
        LDSM_X4(qh0, qbase + ks * 32);
        LDSM_X4(qh1, qbase + (uint32_t)(16 * RS) + ks * 32);
        MMA_F16_2(S[0][0], qh0, bk0[0], bk0[1]);   // q x k_hi
        MMA_F16_2(S[1][0], qh1, bk0[0], bk0[1]);
        MMA_F16_2(S[0][1], qh0, bk1[0], bk1[1]);
        MMA_F16_2(S[1][1], qh1, bk1[0], bk1[1]);
        MMA_F16_2(S[0][0], qh0, bk0[2], bk0[3]);   // q x k_lo
        MMA_F16_2(S[1][0], qh1, bk0[2], bk0[3]);
        MMA_F16_2(S[0][1], qh0, bk1[2], bk1[3]);
        MMA_F16_2(S[1][1], qh1, bk1[2], bk1[3]);
    }
}

__global__ __launch_bounds__(128, 2) void attn_kernel() {
    extern __shared__ char smem[];
    const int tid = threadIdx.x;
    const int wid = tid >> 5, lane = tid & 31;
    const int qr = lane >> 2, qc = lane & 3;
    const int i0 = blockIdx.x * 128, h = blockIdx.y, b = blockIdx.z;
    const size_t bh = (size_t)b * HEADS + h;

    const uint32_t sb = smem_u32(smem);
    const uint32_t aOff = (uint32_t)((lane & 15) * RS + (lane >> 4) * 16);
    const uint32_t bOff = (uint32_t)((lane >> 4) * 9216 + ((lane >> 3) & 1) * 16 + (lane & 7) * RS);
    const uint32_t qBase = sb + (uint32_t)(wid * 32) * RS + aOff;

    const __half* khp = g_kh + bh * N * DH;
    const __half* klp = g_kl + bh * N * DH;
    const __half* vhp = g_vh + bh * DH * N;
    const __half* vlp = g_vl + bh * DH * N;

    // ---- stage Q plane into persistent smem region ----
    const __half* qfp = g_qf + (bh * N + i0) * DH;
    #pragma unroll
    for (int it = 0; it < 8; it++) {
        int idx = tid + it * 128;          // 1024 uint4
        int row = idx >> 3, ch = idx & 7;
        uint32_t so = (uint32_t)row * RS + ch * 16;
        *(uint4*)(smem + so) = *(const uint4*)(qfp + (size_t)row * DH + ch * 8);
    }

    float O[2][8][4] = {};
    float ls0[2] = {0.f, 0.f}, ls1[2] = {0.f, 0.f};

    for (int tile = 0; tile < 32; tile++) {
        const int j0 = tile * 64;
        char* bb = smem + 18432 + (tile & 1) * 36864;
        #pragma unroll
        for (int it = 0; it < 4; it++) {
            int idx = tid + it * 128;      // 512 uint4 per plane
            int row = idx >> 3, ch = idx & 7;
            uint32_t so = (uint32_t)row * RS + ch * 16;
            *(uint4*)(bb + so)         = *(const uint4*)(khp + (size_t)(j0 + row) * DH + ch * 8);
            *(uint4*)(bb + 9216 + so)  = *(const uint4*)(klp + (size_t)(j0 + row) * DH + ch * 8);
            *(uint4*)(bb + 18432 + so) = *(const uint4*)(vhp + (size_t)row * N + j0 + ch * 8);
            *(uint4*)(bb + 27648 + so) = *(const uint4*)(vlp + (size_t)row * N + j0 + ch * 8);
        }
        __syncthreads();   // also covers Q staging on tile 0

        const uint32_t kB = sb + 18432u + (uint32_t)((tile & 1) * 36864) + bOff;
        const uint32_t vB = kB + 18432u;

        float S[2][2][2][4];   // [parity][m][nn][4]
        qk_burst(S[0], kB, qBase);

        #pragma unroll
        for (int pr = 0; pr < 4; pr++) {
            const int cur = pr & 1;
            if (pr < 3)
                qk_burst(S[cur ^ 1], kB + (uint32_t)((pr + 1) * 16) * RS, qBase);

            // softmax(pr): max-free exp; P single fp16 plane (no split)
            uint32_t pa[2][4];
            #pragma unroll
            for (int m = 0; m < 2; m++)
                #pragma unroll
                for (int nn = 0; nn < 2; nn++) {
                    float p0 = __expf(S[cur][m][nn][0]), p1 = __expf(S[cur][m][nn][1]);
                    float p2 = __expf(S[cur][m][nn][2]), p3 = __expf(S[cur][m][nn][3]);
                    ls0[m] += p0 + p1;
                    ls1[m] += p2 + p3;
                    pa[m][nn * 2 + 0] = pack_f16(p0, p1);
                    pa[m][nn * 2 + 1] = pack_f16(p2, p3);
                }
            // PV(pr): O += P x (v_hi, v_lo)
            #pragma unroll
            for (int ndp = 0; ndp < 4; ndp++) {
                const int n0 = ndp * 2, n1 = ndp * 2 + 1;
                uint32_t bv0[4], bv1[4];
                LDSM_X4(bv0, vB + (uint32_t)n0 * (8 * RS) + pr * 32);
                LDSM_X4(bv1, vB + (uint32_t)n1 * (8 * RS) + pr * 32);
                MMA_F16_2(O[0][n0], pa[0], bv0[0], bv0[1]);
                MMA_F16_2(O[1][n0], pa[1], bv0[0], bv0[1]);
                MMA_F16_2(O[0][n1], pa[0], bv1[0], bv1[1]);
                MMA_F16_2(O[1][n1], pa[1], bv1[0], bv1[1]);
                MMA_F16_2(O[0][n0], pa[0], bv0[2], bv0[3]);
                MMA_F16_2(O[1][n0], pa[1], bv0[2], bv0[3]);
                MMA_F16_2(O[0][n1], pa[0], bv1[2], bv1[3]);
                MMA_F16_2(O[1][n1], pa[1], bv1[2], bv1[3]);
            }
        }
    }

    #pragma unroll
    for (int m = 0; m < 2; m++) {
        ls0[m] += __shfl_xor_sync(0xffffffffu, ls0[m], 1);
        ls0[m] += __shfl_xor_sync(0xffffffffu, ls0[m], 2);
        ls1[m] += __shfl_xor_sync(0xffffffffu, ls1[m], 1);
        ls1[m] += __shfl_xor_sync(0xffffffffu, ls1[m], 2);
    }

    // ---- epilogue: normalized bf16 hi/lo -> g_ah/g_al [b][t][c] ----
    #pragma unroll
    for (int m = 0; m < 2; m++) {
        const float inv0 = 1.f / ls0[m], inv1 = 1.f / ls1[m];
        size_t r0 = ((size_t)b * N + i0 + wid * 32 + m * 16 + qr) * HID + h * DH;
        size_t r1 = r0 + 8 * HID;
        #pragma unroll
        for (int nd = 0; nd < 8; nd++) {
            const int d = nd * 8 + qc * 2;
            float v0 = O[m][nd][0] * inv0, v1 = O[m][nd][1] * inv0;
            float v2 = O[m][nd][2] * inv1, v3 = O[m][nd][3] * inv1;
            float h0 = bf16_round(v0), h1 = bf16_round(v1);
            float h2 = bf16_round(v2), h3 = bf16_round(v3);
            *(uint32_t*)&g_ah[r0 + d] = pack_bf16(h0, h1);
            *(uint32_t*)&g_al[r0 + d] = pack_bf16(v0 - h0, v1 - h1);
            *(uint32_t*)&g_ah[r1 + d] = pack_bf16(h2, h3);
            *(uint32_t*)&g_al[r1 + d] = pack_bf16(v2 - h2, v3 - h3);
        }
    }
}

// ---------------------------------------------------------------------------
extern "C" void kernel_launch(void* const* d_in, const int* in_sizes, int n_in,
                              void* d_out, int out_size) {
    const float* x     = (const float*)d_in[0];
    const float* w_qkv = (const float*)d_in[1];
    const float* w_out = (const float*)d_in[2];
    const float* b_out = (const float*)d_in[3];
    float* out = (float*)d_out;

    cudaFuncSetAttribute(gemm_kernel<DIM, 0>,
                         cudaFuncAttributeMaxDynamicSharedMemorySize, SM_GEMM);
    cudaFuncSetAttribute(gemm_kernel<HID, 1>,
                         cudaFuncAttributeMaxDynamicSharedMemorySize, SM_GEMM);
    cudaFuncSetAttribute(attn_kernel,
                         cudaFuncAttributeMaxDynamicSharedMemorySize, SM_ATTN);

    split_w<<<(3 * HID * DIM + DIM * HID) / 256, 256>>>(w_qkv, w_out);
    split_x<<<dim3(N / 64, DIM / 64, B), 256>>>(x);
    gemm_kernel<DIM, 0><<<dim3(N / 64, 3 * HID / 128, B), 128, SM_GEMM>>>(nullptr, nullptr);
    attn_kernel<<<dim3(N / 128, HEADS, B), 128, SM_ATTN>>>();
    gemm_kernel<HID, 1><<<dim3(N / 64, DIM / 128, B), 128, SM_GEMM>>>(b_out, out);
}

// round 15
// speedup vs baseline: 1.5076x; 1.1698x over previous
#include <cuda_runtime.h>
#include <cuda_bf16.h>
#include <cuda_fp16.h>
#include <cstdint>
#include <math.h>

#define B     4
#define DIM   256
#define N     2048
#define HEADS 8
#define DH    64
#define HID   512
#define QK_SCALE 0.125f

typedef __nv_bfloat16 bf16;

// ---------------- scratch planes (device globals; no allocations) -----------
__device__ bf16 g_wqh[3 * HID * DIM], g_wql[3 * HID * DIM];   // [1536][256]
__device__ bf16 g_woh[DIM * HID],     g_wol[DIM * HID];       // [256][512]
__device__ bf16 g_xh[(size_t)B * N * DIM],  g_xl[(size_t)B * N * DIM];   // [b][t][k]
// attention operands: fp16 (q single plane, k hi+lo, v single plane)
__device__ __half g_qf[(size_t)B * HEADS * N * DH];                       // [b,h][t][d]
__device__ __half g_kh[(size_t)B * HEADS * N * DH], g_kl[(size_t)B * HEADS * N * DH];
__device__ __half g_vf[(size_t)B * HEADS * DH * N];                       // [b,h][d][t]
__device__ bf16 g_ah[(size_t)B * N * HID], g_al[(size_t)B * N * HID];    // [b][t][c]

// ============================ helpers =======================================
__device__ __forceinline__ uint32_t pack_bf16(float lo, float hi) {
    uint32_t r;
    asm("cvt.rn.bf16x2.f32 %0, %1, %2;" : "=r"(r) : "f"(hi), "f"(lo));
    return r;
}
__device__ __forceinline__ float bf16_round(float x) {
    return __bfloat162float(__float2bfloat16(x));
}
__device__ __forceinline__ uint32_t pack_f16(float lo, float hi) {
    __half2 h = __floats2half2_rn(lo, hi);   // lo -> low half
    return *(uint32_t*)&h;
}
__device__ __forceinline__ uint32_t smem_u32(const void* p) {
    uint32_t a;
    asm("{ .reg .u64 t; cvta.to.shared.u64 t, %1; cvt.u32.u64 %0, t; }" : "=r"(a) : "l"(p));
    return a;
}

#define MMA_BF16_2(C, A, b0, b1)                                               \
    asm volatile(                                                              \
        "mma.sync.aligned.m16n8k16.row.col.f32.bf16.bf16.f32 "                 \
        "{%0,%1,%2,%3}, {%4,%5,%6,%7}, {%8,%9}, {%0,%1,%2,%3};"                \
        : "+f"((C)[0]), "+f"((C)[1]), "+f"((C)[2]), "+f"((C)[3])               \
        : "r"((A)[0]), "r"((A)[1]), "r"((A)[2]), "r"((A)[3]),                  \
          "r"(b0), "r"(b1))

#define MMA_F16_2(C, A, b0, b1)                                                \
    asm volatile(                                                              \
        "mma.sync.aligned.m16n8k16.row.col.f32.f16.f16.f32 "                   \
        "{%0,%1,%2,%3}, {%4,%5,%6,%7}, {%8,%9}, {%0,%1,%2,%3};"                \
        : "+f"((C)[0]), "+f"((C)[1]), "+f"((C)[2]), "+f"((C)[3])               \
        : "r"((A)[0]), "r"((A)[1]), "r"((A)[2]), "r"((A)[3]),                  \
          "r"(b0), "r"(b1))

#define LDSM_X4(R, a)                                                          \
    asm volatile("ldmatrix.sync.aligned.m8n8.x4.shared.b16 {%0,%1,%2,%3}, [%4];" \
        : "=r"((R)[0]), "=r"((R)[1]), "=r"((R)[2]), "=r"((R)[3]) : "r"(a))

#define RS 144   // smem row stride bytes (72 elems): conflict-free ldmatrix

// ======================= split kernels (run once per launch) ================
__global__ __launch_bounds__(256) void split_w(const float* __restrict__ wq,
                                               const float* __restrict__ wo) {
    int i = blockIdx.x * 256 + threadIdx.x;
    const int NQ = 3 * HID * DIM;
    if (i < NQ) {
        float v = wq[i], hi = bf16_round(v);
        g_wqh[i] = __float2bfloat16(hi);
        g_wql[i] = __float2bfloat16(v - hi);
    } else {
        int j = i - NQ;
        float v = wo[j], hi = bf16_round(v);
        g_woh[j] = __float2bfloat16(hi);
        g_wol[j] = __float2bfloat16(v - hi);
    }
}

// x [b][k][t] fp32 -> g_xh/g_xl [b][t][k] bf16 (64x64 smem transpose tiles)
__global__ __launch_bounds__(256) void split_x(const float* __restrict__ x) {
    __shared__ float ts[64][65];
    const int t0 = blockIdx.x * 64, k0 = blockIdx.y * 64, b = blockIdx.z;
    const int tid = threadIdx.x;
    #pragma unroll
    for (int it = 0; it < 4; it++) {
        int idx = tid + it * 256;
        int kr = idx >> 4, t4 = idx & 15;
        float4 v = *(const float4*)&x[(size_t)b * DIM * N + (size_t)(k0 + kr) * N + t0 + t4 * 4];
        ts[kr][t4 * 4 + 0] = v.x; ts[kr][t4 * 4 + 1] = v.y;
        ts[kr][t4 * 4 + 2] = v.z; ts[kr][t4 * 4 + 3] = v.w;
    }
    __syncthreads();
    #pragma unroll
    for (int it = 0; it < 8; it++) {
        int idx = tid + it * 256;
        int tr = idx >> 5, kp = idx & 31;
        float e0 = ts[kp * 2][tr], e1 = ts[kp * 2 + 1][tr];
        float h0 = bf16_round(e0), h1 = bf16_round(e1);
        size_t a = (size_t)b * N * DIM + (size_t)(t0 + tr) * DIM + k0 + kp * 2;
        *(uint32_t*)&g_xh[a] = pack_bf16(h0, h1);
        *(uint32_t*)&g_xl[a] = pack_bf16(e0 - h0, e1 - h1);
    }
}

// ================ GEMM: dst[o,t] = sum_k w[o,k] src[t,k]  (bf16 3-term) =====
// CTA 128o x 64t, 128 threads / 4 warps; warp owns 32 o rows (2 m16 tiles).
#define SM_GEMM 55296

template<int KTOT, int EPI>
__global__ __launch_bounds__(128, 2) void gemm_kernel(
        const float* __restrict__ bias, float* __restrict__ dst) {
    extern __shared__ char smem[];
    const int tid = threadIdx.x;
    const int wid = tid >> 5, lane = tid & 31;
    const int qr = lane >> 2, qc = lane & 3;
    const int t0 = blockIdx.x * 64, o0 = blockIdx.y * 128, b = blockIdx.z;

    const bf16* wh = (EPI == 0) ? g_wqh : g_woh;
    const bf16* wl = (EPI == 0) ? g_wql : g_wol;
    const bf16* xh = (EPI == 0) ? g_xh  : g_ah;
    const bf16* xl = (EPI == 0) ? g_xl  : g_al;

    const uint32_t sb = smem_u32(smem);
    const uint32_t aOff = (uint32_t)((lane & 15) * RS + (lane >> 4) * 16);
    const uint32_t bOff = (uint32_t)((lane >> 4) * 9216 + ((lane >> 3) & 1) * 16 + (lane & 7) * RS);
    const uint32_t wA = sb + (uint32_t)(wid * 32) * RS + aOff;
    const uint32_t xB = sb + 36864u + bOff;

    const bf16* xhb = xh + (size_t)b * N * KTOT;
    const bf16* xlb = xl + (size_t)b * N * KTOT;
    float C[2][8][4] = {};

    for (int k0 = 0; k0 < KTOT; k0 += 64) {
        __syncthreads();
        #pragma unroll
        for (int it = 0; it < 8; it++) {
            int idx = tid + it * 128;
            int row = idx >> 3, ch = idx & 7;
            uint32_t so = (uint32_t)row * RS + ch * 16;
            *(uint4*)(smem + so) =
                *(const uint4*)(wh + (size_t)(o0 + row) * KTOT + k0 + ch * 8);
            *(uint4*)(smem + 18432 + so) =
                *(const uint4*)(wl + (size_t)(o0 + row) * KTOT + k0 + ch * 8);
        }
        #pragma unroll
        for (int it = 0; it < 4; it++) {
            int idx = tid + it * 128;
            int row = idx >> 3, ch = idx & 7;
            uint32_t so = (uint32_t)row * RS + ch * 16;
            *(uint4*)(smem + 36864 + so) =
                *(const uint4*)(xhb + (size_t)(t0 + row) * KTOT + k0 + ch * 8);
            *(uint4*)(smem + 46080 + so) =
                *(const uint4*)(xlb + (size_t)(t0 + row) * KTOT + k0 + ch * 8);
        }
        __syncthreads();

        uint32_t awh[2][4][4], awl[2][4][4];
        #pragma unroll
        for (int m = 0; m < 2; m++)
            #pragma unroll
            for (int ks = 0; ks < 4; ks++) {
                LDSM_X4(awh[m][ks], wA + (uint32_t)m * (16 * RS) + ks * 32);
                LDSM_X4(awl[m][ks], wA + 18432u + (uint32_t)m * (16 * RS) + ks * 32);
            }
        #pragma unroll
        for (int np = 0; np < 4; np++) {
            const int n0 = np * 2, n1 = np * 2 + 1;
            uint32_t bx0[4][4], bx1[4][4];
            #pragma unroll
            for (int ks = 0; ks < 4; ks++) {
                LDSM_X4(bx0[ks], xB + (uint32_t)n0 * (8 * RS) + ks * 32);
                LDSM_X4(bx1[ks], xB + (uint32_t)n1 * (8 * RS) + ks * 32);
            }
            #pragma unroll
            for (int ks = 0; ks < 4; ks++) {
                MMA_BF16_2(C[0][n0], awh[0][ks], bx0[ks][0], bx0[ks][1]);
                MMA_BF16_2(C[1][n0], awh[1][ks], bx0[ks][0], bx0[ks][1]);
                MMA_BF16_2(C[0][n1], awh[0][ks], bx1[ks][0], bx1[ks][1]);
                MMA_BF16_2(C[1][n1], awh[1][ks], bx1[ks][0], bx1[ks][1]);
                MMA_BF16_2(C[0][n0], awh[0][ks], bx0[ks][2], bx0[ks][3]);
                MMA_BF16_2(C[1][n0], awh[1][ks], bx0[ks][2], bx0[ks][3]);
                MMA_BF16_2(C[0][n1], awh[0][ks], bx1[ks][2], bx1[ks][3]);
                MMA_BF16_2(C[1][n1], awh[1][ks], bx1[ks][2], bx1[ks][3]);
                MMA_BF16_2(C[0][n0], awl[0][ks], bx0[ks][0], bx0[ks][1]);
                MMA_BF16_2(C[1][n0], awl[1][ks], bx0[ks][0], bx0[ks][1]);
                MMA_BF16_2(C[0][n1], awl[0][ks], bx1[ks][0], bx1[ks][1]);
                MMA_BF16_2(C[1][n1], awl[1][ks], bx1[ks][0], bx1[ks][1]);
            }
        }
    }

    if (EPI == 1) {
        float* db = dst + (size_t)b * DIM * N;
        #pragma unroll
        for (int m = 0; m < 2; m++) {
            const int r0 = o0 + wid * 32 + m * 16 + qr;
            float b0 = bias[r0], b1 = bias[r0 + 8];
            #pragma unroll
            for (int nt = 0; nt < 8; nt++) {
                const int t = t0 + nt * 8 + qc * 2;
                *(float2*)&db[(size_t)r0 * N + t] =
                    make_float2(C[m][nt][0] + b0, C[m][nt][1] + b0);
                *(float2*)&db[(size_t)(r0 + 8) * N + t] =
                    make_float2(C[m][nt][2] + b1, C[m][nt][3] + b1);
            }
        }
    } else {
        const int type = o0 >> 9;                          // 0:q 1:k 2:v
        #pragma unroll
        for (int m = 0; m < 2; m++) {
            const int oo = (o0 & 511) + wid * 32 + m * 16;
            const int hh = oo >> 6;                        // uniform per warp-half
            const int d0 = (oo & 63) + qr;
            const size_t bh = (size_t)b * HEADS + hh;
            if (type == 0) {
                #pragma unroll
                for (int nt = 0; nt < 8; nt++) {
                    const int t = t0 + nt * 8 + qc * 2;
                    size_t a = (bh * N + t) * DH + d0;
                    g_qf[a]          = __float2half(C[m][nt][0] * QK_SCALE);
                    g_qf[a + DH]     = __float2half(C[m][nt][1] * QK_SCALE);
                    g_qf[a + 8]      = __float2half(C[m][nt][2] * QK_SCALE);
                    g_qf[a + DH + 8] = __float2half(C[m][nt][3] * QK_SCALE);
                }
            } else if (type == 1) {
                #pragma unroll
                for (int nt = 0; nt < 8; nt++) {
                    const int t = t0 + nt * 8 + qc * 2;
                    size_t a = (bh * N + t) * DH + d0;
                    float v0 = C[m][nt][0], v1 = C[m][nt][1];
                    float v2 = C[m][nt][2], v3 = C[m][nt][3];
                    __half h0 = __float2half(v0), h1 = __float2half(v1);
                    __half h2 = __float2half(v2), h3 = __float2half(v3);
                    g_kh[a]          = h0; g_kl[a]          = __float2half(v0 - __half2float(h0));
                    g_kh[a + DH]     = h1; g_kl[a + DH]     = __float2half(v1 - __half2float(h1));
                    g_kh[a + 8]      = h2; g_kl[a + 8]      = __float2half(v2 - __half2float(h2));
                    g_kh[a + DH + 8] = h3; g_kl[a + DH + 8] = __float2half(v3 - __half2float(h3));
                }
            } else {
                // v: single fp16 plane, [d][t]
                #pragma unroll
                for (int nt = 0; nt < 8; nt++) {
                    const int t = t0 + nt * 8 + qc * 2;
                    size_t a0 = (bh * DH + d0) * N + t;
                    size_t a1 = (bh * DH + d0 + 8) * N + t;
                    *(uint32_t*)&g_vf[a0] = pack_f16(C[m][nt][0], C[m][nt][1]);
                    *(uint32_t*)&g_vf[a1] = pack_f16(C[m][nt][2], C[m][nt][3]);
                }
            }
        }
    }
}

// == attention: fp16, q/p/v single-plane, k hi/lo; pr-pipelined =============
// CTA: 128 q x (b,h). 128 threads / 4 warps, 32 q/warp. 64-key tiles.
// smem: Q @0 (18432, persistent); buf(i) @18432+i*27648:
//       {kh 0, kl 9216, vf 18432}. Total 73728 (2 CTAs = 144KB).
#define SM_ATTN 73728

__device__ __forceinline__ void qk_burst(float (&S)[2][2][4], uint32_t kbase,
                                         uint32_t qbase) {
    #pragma unroll
    for (int m = 0; m < 2; m++)
        #pragma unroll
        for (int nn = 0; nn < 2; nn++)
            #pragma unroll
            for (int i = 0; i < 4; i++) S[m][nn][i] = 0.f;
    #pragma unroll
    for (int ks = 0; ks < 4; ks++) {
        uint32_t bk0[4], bk1[4], qh0[4], qh1[4];
        LDSM_X4(bk0, kbase + ks * 32);
        LDSM_X4(bk1, kbase + (uint32_t)(8 * RS) + ks * 32);
        LDSM_X4(qh0, qbase + ks * 32);
        LDSM_X4(qh1, qbase + (uint32_t)(16 * RS) + ks * 32);
        MMA_F16_2(S[0][0], qh0, bk0[0], bk0[1]);   // q x k_hi
        MMA_F16_2(S[1][0], qh1, bk0[0], bk0[1]);
        MMA_F16_2(S[0][1], qh0, bk1[0], bk1[1]);
        MMA_F16_2(S[1][1], qh1, bk1[0], bk1[1]);
        MMA_F16_2(S[0][0], qh0, bk0[2], bk0[3]);   // q x k_lo
        MMA_F16_2(S[1][0], qh1, bk0[2], bk0[3]);
        MMA_F16_2(S[0][1], qh0, bk1[2], bk1[3]);
        MMA_F16_2(S[1][1], qh1, bk1[2], bk1[3]);
    }
}

__global__ __launch_bounds__(128, 2) void attn_kernel() {
    extern __shared__ char smem[];
    const int tid = threadIdx.x;
    const int wid = tid >> 5, lane = tid & 31;
    const int qr = lane >> 2, qc = lane & 3;
    const int i0 = blockIdx.x * 128, h = blockIdx.y, b = blockIdx.z;
    const size_t bh = (size_t)b * HEADS + h;

    const uint32_t sb = smem_u32(smem);
    const uint32_t aOff = (uint32_t)((lane & 15) * RS + (lane >> 4) * 16);
    // K fragments: hi/lo planes 9216 apart (lanes 16-31 -> lo)
    const uint32_t bOff = (uint32_t)((lane >> 4) * 9216 + ((lane >> 3) & 1) * 16 + (lane & 7) * RS);
    // V fragments: single plane; lanes 16-31 -> NEXT n-tile (rows +8)
    const uint32_t vOff = (uint32_t)((lane >> 4) * (8 * RS) + ((lane >> 3) & 1) * 16 + (lane & 7) * RS);
    const uint32_t qBase = sb + (uint32_t)(wid * 32) * RS + aOff;

    const __half* khp = g_kh + bh * N * DH;
    const __half* klp = g_kl + bh * N * DH;
    const __half* vfp = g_vf + bh * DH * N;

    // ---- stage Q plane into persistent smem region ----
    const __half* qfp = g_qf + (bh * N + i0) * DH;
    #pragma unroll
    for (int it = 0; it < 8; it++) {
        int idx = tid + it * 128;          // 1024 uint4
        int row = idx >> 3, ch = idx & 7;
        uint32_t so = (uint32_t)row * RS + ch * 16;
        *(uint4*)(smem + so) = *(const uint4*)(qfp + (size_t)row * DH + ch * 8);
    }

    float O[2][8][4] = {};
    float ls0[2] = {0.f, 0.f}, ls1[2] = {0.f, 0.f};

    for (int tile = 0; tile < 32; tile++) {
        const int j0 = tile * 64;
        char* bb = smem + 18432 + (tile & 1) * 27648;
        #pragma unroll
        for (int it = 0; it < 4; it++) {
            int idx = tid + it * 128;      // 512 uint4 per plane
            int row = idx >> 3, ch = idx & 7;
            uint32_t so = (uint32_t)row * RS + ch * 16;
            *(uint4*)(bb + so)         = *(const uint4*)(khp + (size_t)(j0 + row) * DH + ch * 8);
            *(uint4*)(bb + 9216 + so)  = *(const uint4*)(klp + (size_t)(j0 + row) * DH + ch * 8);
            *(uint4*)(bb + 18432 + so) = *(const uint4*)(vfp + (size_t)row * N + j0 + ch * 8);
        }
        __syncthreads();   // also covers Q staging on tile 0

        const uint32_t base = sb + 18432u + (uint32_t)((tile & 1) * 27648);
        const uint32_t kB = base + bOff;
        const uint32_t vB = base + 18432u + vOff;

        float S[2][2][2][4];   // [parity][m][nn][4]
        qk_burst(S[0], kB, qBase);

        #pragma unroll
        for (int pr = 0; pr < 4; pr++) {
            const int cur = pr & 1;
            if (pr < 3)
                qk_burst(S[cur ^ 1], kB + (uint32_t)((pr + 1) * 16) * RS, qBase);

            // softmax(pr): max-free exp; P single fp16 plane
            uint32_t pa[2][4];
            #pragma unroll
            for (int m = 0; m < 2; m++)
                #pragma unroll
                for (int nn = 0; nn < 2; nn++) {
                    float p0 = __expf(S[cur][m][nn][0]), p1 = __expf(S[cur][m][nn][1]);
                    float p2 = __expf(S[cur][m][nn][2]), p3 = __expf(S[cur][m][nn][3]);
                    ls0[m] += p0 + p1;
                    ls1[m] += p2 + p3;
                    pa[m][nn * 2 + 0] = pack_f16(p0, p1);
                    pa[m][nn * 2 + 1] = pack_f16(p2, p3);
                }
            // PV(pr): O += P x V, single plane, 1 LDSM per nd-pair
            #pragma unroll
            for (int ndp = 0; ndp < 4; ndp++) {
                const int n0 = ndp * 2, n1 = ndp * 2 + 1;
                uint32_t bv[4];
                LDSM_X4(bv, vB + (uint32_t)ndp * (16 * RS) + pr * 32);
                MMA_F16_2(O[0][n0], pa[0], bv[0], bv[1]);
                MMA_F16_2(O[1][n0], pa[1], bv[0], bv[1]);
                MMA_F16_2(O[0][n1], pa[0], bv[2], bv[3]);
                MMA_F16_2(O[1][n1], pa[1], bv[2], bv[3]);
            }
        }
    }

    #pragma unroll
    for (int m = 0; m < 2; m++) {
        ls0[m] += __shfl_xor_sync(0xffffffffu, ls0[m], 1);
        ls0[m] += __shfl_xor_sync(0xffffffffu, ls0[m], 2);
        ls1[m] += __shfl_xor_sync(0xffffffffu, ls1[m], 1);
        ls1[m] += __shfl_xor_sync(0xffffffffu, ls1[m], 2);
    }

    // ---- epilogue: normalized bf16 hi/lo -> g_ah/g_al [b][t][c] ----
    #pragma unroll
    for (int m = 0; m < 2; m++) {
        const float inv0 = 1.f / ls0[m], inv1 = 1.f / ls1[m];
        size_t r0 = ((size_t)b * N + i0 + wid * 32 + m * 16 + qr) * HID + h * DH;
        size_t r1 = r0 + 8 * HID;
        #pragma unroll
        for (int nd = 0; nd < 8; nd++) {
            const int d = nd * 8 + qc * 2;
            float v0 = O[m][nd][0] * inv0, v1 = O[m][nd][1] * inv0;
            float v2 = O[m][nd][2] * inv1, v3 = O[m][nd][3] * inv1;
            float h0 = bf16_round(v0), h1 = bf16_round(v1);
            float h2 = bf16_round(v2), h3 = bf16_round(v3);
            *(uint32_t*)&g_ah[r0 + d] = pack_bf16(h0, h1);
            *(uint32_t*)&g_al[r0 + d] = pack_bf16(v0 - h0, v1 - h1);
            *(uint32_t*)&g_ah[r1 + d] = pack_bf16(h2, h3);
            *(uint32_t*)&g_al[r1 + d] = pack_bf16(v2 - h2, v3 - h3);
        }
    }
}

// ---------------------------------------------------------------------------
extern "C" void kernel_launch(void* const* d_in, const int* in_sizes, int n_in,
                              void* d_out, int out_size) {
    const float* x     = (const float*)d_in[0];
    const float* w_qkv = (const float*)d_in[1];
    const float* w_out = (const float*)d_in[2];
    const float* b_out = (const float*)d_in[3];
    float* out = (float*)d_out;

    cudaFuncSetAttribute(gemm_kernel<DIM, 0>,
                         cudaFuncAttributeMaxDynamicSharedMemorySize, SM_GEMM);
    cudaFuncSetAttribute(gemm_kernel<HID, 1>,
                         cudaFuncAttributeMaxDynamicSharedMemorySize, SM_GEMM);
    cudaFuncSetAttribute(attn_kernel,
                         cudaFuncAttributeMaxDynamicSharedMemorySize, SM_ATTN);

    split_w<<<(3 * HID * DIM + DIM * HID) / 256, 256>>>(w_qkv, w_out);
    split_x<<<dim3(N / 64, DIM / 64, B), 256>>>(x);
    gemm_kernel<DIM, 0><<<dim3(N / 64, 3 * HID / 128, B), 128, SM_GEMM>>>(nullptr, nullptr);
    attn_kernel<<<dim3(N / 128, HEADS, B), 128, SM_ATTN>>>();
    gemm_kernel<HID, 1><<<dim3(N / 64, DIM / 128, B), 128, SM_GEMM>>>(b_out, out);
}

// round 16
// speedup vs baseline: 1.7765x; 1.1784x over previous
#include <cuda_runtime.h>
#include <cuda_bf16.h>
#include <cuda_fp16.h>
#include <cstdint>
#include <math.h>

#define B     4
#define DIM   256
#define N     2048
#define HEADS 8
#define DH    64
#define HID   512
#define QK_SCALE 0.125f

typedef __nv_bfloat16 bf16;

// ---------------- scratch planes (device globals; no allocations) -----------
__device__ bf16 g_wqh[3 * HID * DIM], g_wql[3 * HID * DIM];   // [1536][256]
__device__ bf16 g_woh[DIM * HID],     g_wol[DIM * HID];       // [256][512]
__device__ bf16 g_xh[(size_t)B * N * DIM],  g_xl[(size_t)B * N * DIM];   // [b][t][k]
// attention operands: all single fp16 planes (q pre-scaled)
__device__ __half g_qf[(size_t)B * HEADS * N * DH];           // [b,h][t][d]
__device__ __half g_kf[(size_t)B * HEADS * N * DH];           // [b,h][t][d]
__device__ __half g_vf[(size_t)B * HEADS * DH * N];           // [b,h][d][t]
__device__ bf16 g_ah[(size_t)B * N * HID], g_al[(size_t)B * N * HID];    // [b][t][c]

// ============================ helpers =======================================
__device__ __forceinline__ uint32_t pack_bf16(float lo, float hi) {
    uint32_t r;
    asm("cvt.rn.bf16x2.f32 %0, %1, %2;" : "=r"(r) : "f"(hi), "f"(lo));
    return r;
}
__device__ __forceinline__ float bf16_round(float x) {
    return __bfloat162float(__float2bfloat16(x));
}
__device__ __forceinline__ uint32_t pack_f16(float lo, float hi) {
    __half2 h = __floats2half2_rn(lo, hi);   // lo -> low half
    return *(uint32_t*)&h;
}
__device__ __forceinline__ uint32_t smem_u32(const void* p) {
    uint32_t a;
    asm("{ .reg .u64 t; cvta.to.shared.u64 t, %1; cvt.u32.u64 %0, t; }" : "=r"(a) : "l"(p));
    return a;
}

#define MMA_BF16_2(C, A, b0, b1)                                               \
    asm volatile(                                                              \
        "mma.sync.aligned.m16n8k16.row.col.f32.bf16.bf16.f32 "                 \
        "{%0,%1,%2,%3}, {%4,%5,%6,%7}, {%8,%9}, {%0,%1,%2,%3};"                \
        : "+f"((C)[0]), "+f"((C)[1]), "+f"((C)[2]), "+f"((C)[3])               \
        : "r"((A)[0]), "r"((A)[1]), "r"((A)[2]), "r"((A)[3]),                  \
          "r"(b0), "r"(b1))

#define MMA_F16_2(C, A, b0, b1)                                                \
    asm volatile(                                                              \
        "mma.sync.aligned.m16n8k16.row.col.f32.f16.f16.f32 "                   \
        "{%0,%1,%2,%3}, {%4,%5,%6,%7}, {%8,%9}, {%0,%1,%2,%3};"                \
        : "+f"((C)[0]), "+f"((C)[1]), "+f"((C)[2]), "+f"((C)[3])               \
        : "r"((A)[0]), "r"((A)[1]), "r"((A)[2]), "r"((A)[3]),                  \
          "r"(b0), "r"(b1))

#define LDSM_X4(R, a)                                                          \
    asm volatile("ldmatrix.sync.aligned.m8n8.x4.shared.b16 {%0,%1,%2,%3}, [%4];" \
        : "=r"((R)[0]), "=r"((R)[1]), "=r"((R)[2]), "=r"((R)[3]) : "r"(a))

#define RS 144   // smem row stride bytes (72 elems): conflict-free ldmatrix

// ======================= split kernels (run once per launch) ================
__global__ __launch_bounds__(256) void split_w(const float* __restrict__ wq,
                                               const float* __restrict__ wo) {
    int i = blockIdx.x * 256 + threadIdx.x;
    const int NQ = 3 * HID * DIM;
    if (i < NQ) {
        float v = wq[i], hi = bf16_round(v);
        g_wqh[i] = __float2bfloat16(hi);
        g_wql[i] = __float2bfloat16(v - hi);
    } else {
        int j = i - NQ;
        float v = wo[j], hi = bf16_round(v);
        g_woh[j] = __float2bfloat16(hi);
        g_wol[j] = __float2bfloat16(v - hi);
    }
}

// x [b][k][t] fp32 -> g_xh/g_xl [b][t][k] bf16 (64x64 smem transpose tiles)
__global__ __launch_bounds__(256) void split_x(const float* __restrict__ x) {
    __shared__ float ts[64][65];
    const int t0 = blockIdx.x * 64, k0 = blockIdx.y * 64, b = blockIdx.z;
    const int tid = threadIdx.x;
    #pragma unroll
    for (int it = 0; it < 4; it++) {
        int idx = tid + it * 256;
        int kr = idx >> 4, t4 = idx & 15;
        float4 v = *(const float4*)&x[(size_t)b * DIM * N + (size_t)(k0 + kr) * N + t0 + t4 * 4];
        ts[kr][t4 * 4 + 0] = v.x; ts[kr][t4 * 4 + 1] = v.y;
        ts[kr][t4 * 4 + 2] = v.z; ts[kr][t4 * 4 + 3] = v.w;
    }
    __syncthreads();
    #pragma unroll
    for (int it = 0; it < 8; it++) {
        int idx = tid + it * 256;
        int tr = idx >> 5, kp = idx & 31;
        float e0 = ts[kp * 2][tr], e1 = ts[kp * 2 + 1][tr];
        float h0 = bf16_round(e0), h1 = bf16_round(e1);
        size_t a = (size_t)b * N * DIM + (size_t)(t0 + tr) * DIM + k0 + kp * 2;
        *(uint32_t*)&g_xh[a] = pack_bf16(h0, h1);
        *(uint32_t*)&g_xl[a] = pack_bf16(e0 - h0, e1 - h1);
    }
}

// ================ GEMM: dst[o,t] = sum_k w[o,k] src[t,k]  (bf16 3-term) =====
// CTA 128o x 64t, 128 threads / 4 warps; warp owns 32 o rows (2 m16 tiles).
#define SM_GEMM 55296

template<int KTOT, int EPI>
__global__ __launch_bounds__(128, 2) void gemm_kernel(
        const float* __restrict__ bias, float* __restrict__ dst) {
    extern __shared__ char smem[];
    const int tid = threadIdx.x;
    const int wid = tid >> 5, lane = tid & 31;
    const int qr = lane >> 2, qc = lane & 3;
    const int t0 = blockIdx.x * 64, o0 = blockIdx.y * 128, b = blockIdx.z;

    const bf16* wh = (EPI == 0) ? g_wqh : g_woh;
    const bf16* wl = (EPI == 0) ? g_wql : g_wol;
    const bf16* xh = (EPI == 0) ? g_xh  : g_ah;
    const bf16* xl = (EPI == 0) ? g_xl  : g_al;

    const uint32_t sb = smem_u32(smem);
    const uint32_t aOff = (uint32_t)((lane & 15) * RS + (lane >> 4) * 16);
    const uint32_t bOff = (uint32_t)((lane >> 4) * 9216 + ((lane >> 3) & 1) * 16 + (lane & 7) * RS);
    const uint32_t wA = sb + (uint32_t)(wid * 32) * RS + aOff;
    const uint32_t xB = sb + 36864u + bOff;

    const bf16* xhb = xh + (size_t)b * N * KTOT;
    const bf16* xlb = xl + (size_t)b * N * KTOT;
    float C[2][8][4] = {};

    for (int k0 = 0; k0 < KTOT; k0 += 64) {
        __syncthreads();
        #pragma unroll
        for (int it = 0; it < 8; it++) {
            int idx = tid + it * 128;
            int row = idx >> 3, ch = idx & 7;
            uint32_t so = (uint32_t)row * RS + ch * 16;
            *(uint4*)(smem + so) =
                *(const uint4*)(wh + (size_t)(o0 + row) * KTOT + k0 + ch * 8);
            *(uint4*)(smem + 18432 + so) =
                *(const uint4*)(wl + (size_t)(o0 + row) * KTOT + k0 + ch * 8);
        }
        #pragma unroll
        for (int it = 0; it < 4; it++) {
            int idx = tid + it * 128;
            int row = idx >> 3, ch = idx & 7;
            uint32_t so = (uint32_t)row * RS + ch * 16;
            *(uint4*)(smem + 36864 + so) =
                *(const uint4*)(xhb + (size_t)(t0 + row) * KTOT + k0 + ch * 8);
            *(uint4*)(smem + 46080 + so) =
                *(const uint4*)(xlb + (size_t)(t0 + row) * KTOT + k0 + ch * 8);
        }
        __syncthreads();

        uint32_t awh[2][4][4], awl[2][4][4];
        #pragma unroll
        for (int m = 0; m < 2; m++)
            #pragma unroll
            for (int ks = 0; ks < 4; ks++) {
                LDSM_X4(awh[m][ks], wA + (uint32_t)m * (16 * RS) + ks * 32);
                LDSM_X4(awl[m][ks], wA + 18432u + (uint32_t)m * (16 * RS) + ks * 32);
            }
        #pragma unroll
        for (int np = 0; np < 4; np++) {
            const int n0 = np * 2, n1 = np * 2 + 1;
            uint32_t bx0[4][4], bx1[4][4];
            #pragma unroll
            for (int ks = 0; ks < 4; ks++) {
                LDSM_X4(bx0[ks], xB + (uint32_t)n0 * (8 * RS) + ks * 32);
                LDSM_X4(bx1[ks], xB + (uint32_t)n1 * (8 * RS) + ks * 32);
            }
            #pragma unroll
            for (int ks = 0; ks < 4; ks++) {
                MMA_BF16_2(C[0][n0], awh[0][ks], bx0[ks][0], bx0[ks][1]);
                MMA_BF16_2(C[1][n0], awh[1][ks], bx0[ks][0], bx0[ks][1]);
                MMA_BF16_2(C[0][n1], awh[0][ks], bx1[ks][0], bx1[ks][1]);
                MMA_BF16_2(C[1][n1], awh[1][ks], bx1[ks][0], bx1[ks][1]);
                MMA_BF16_2(C[0][n0], awh[0][ks], bx0[ks][2], bx0[ks][3]);
                MMA_BF16_2(C[1][n0], awh[1][ks], bx0[ks][2], bx0[ks][3]);
                MMA_BF16_2(C[0][n1], awh[0][ks], bx1[ks][2], bx1[ks][3]);
                MMA_BF16_2(C[1][n1], awh[1][ks], bx1[ks][2], bx1[ks][3]);
                MMA_BF16_2(C[0][n0], awl[0][ks], bx0[ks][0], bx0[ks][1]);
                MMA_BF16_2(C[1][n0], awl[1][ks], bx0[ks][0], bx0[ks][1]);
                MMA_BF16_2(C[0][n1], awl[0][ks], bx1[ks][0], bx1[ks][1]);
                MMA_BF16_2(C[1][n1], awl[1][ks], bx1[ks][0], bx1[ks][1]);
            }
        }
    }

    if (EPI == 1) {
        float* db = dst + (size_t)b * DIM * N;
        #pragma unroll
        for (int m = 0; m < 2; m++) {
            const int r0 = o0 + wid * 32 + m * 16 + qr;
            float b0 = bias[r0], b1 = bias[r0 + 8];
            #pragma unroll
            for (int nt = 0; nt < 8; nt++) {
                const int t = t0 + nt * 8 + qc * 2;
                *(float2*)&db[(size_t)r0 * N + t] =
                    make_float2(C[m][nt][0] + b0, C[m][nt][1] + b0);
                *(float2*)&db[(size_t)(r0 + 8) * N + t] =
                    make_float2(C[m][nt][2] + b1, C[m][nt][3] + b1);
            }
        }
    } else {
        const int type = o0 >> 9;                          // 0:q 1:k 2:v
        #pragma unroll
        for (int m = 0; m < 2; m++) {
            const int oo = (o0 & 511) + wid * 32 + m * 16;
            const int hh = oo >> 6;                        // uniform per warp-half
            const int d0 = (oo & 63) + qr;
            const size_t bh = (size_t)b * HEADS + hh;
            if (type != 2) {
                // q, k: single fp16 plane [t][d] (q pre-scaled)
                __half* pf = (type == 0) ? g_qf : g_kf;
                const float s = (type == 0) ? QK_SCALE : 1.f;
                #pragma unroll
                for (int nt = 0; nt < 8; nt++) {
                    const int t = t0 + nt * 8 + qc * 2;
                    size_t a = (bh * N + t) * DH + d0;
                    pf[a]          = __float2half(C[m][nt][0] * s);
                    pf[a + DH]     = __float2half(C[m][nt][1] * s);
                    pf[a + 8]      = __float2half(C[m][nt][2] * s);
                    pf[a + DH + 8] = __float2half(C[m][nt][3] * s);
                }
            } else {
                // v: single fp16 plane [d][t]
                #pragma unroll
                for (int nt = 0; nt < 8; nt++) {
                    const int t = t0 + nt * 8 + qc * 2;
                    size_t a0 = (bh * DH + d0) * N + t;
                    size_t a1 = (bh * DH + d0 + 8) * N + t;
                    *(uint32_t*)&g_vf[a0] = pack_f16(C[m][nt][0], C[m][nt][1]);
                    *(uint32_t*)&g_vf[a1] = pack_f16(C[m][nt][2], C[m][nt][3]);
                }
            }
        }
    }
}

// == attention: all-fp16 single-plane, exact-l softmax; pr-pipelined ========
// CTA: 128 q x (b,h). 128 threads / 4 warps, 32 q/warp. 64-key tiles.
// smem: Q @0 (18432, persistent); buf(i) @18432+i*18432: {kf 0, vf 9216}.
// Total 55296 (2 CTAs = 108KB).
#define SM_ATTN 55296

__device__ __forceinline__ void qk_burst(float (&S)[2][2][4], uint32_t kbase,
                                         uint32_t qbase) {
    #pragma unroll
    for (int m = 0; m < 2; m++)
        #pragma unroll
        for (int nn = 0; nn < 2; nn++)
            #pragma unroll
            for (int i = 0; i < 4; i++) S[m][nn][i] = 0.f;
    #pragma unroll
    for (int ks = 0; ks < 4; ks++) {
        uint32_t bk[4], qh0[4], qh1[4];
        LDSM_X4(bk, kbase + ks * 32);          // n-tile 0 (rows 0-7) + n-tile 1 (rows 8-15)
        LDSM_X4(qh0, qbase + ks * 32);
        LDSM_X4(qh1, qbase + (uint32_t)(16 * RS) + ks * 32);
        MMA_F16_2(S[0][0], qh0, bk[0], bk[1]);
        MMA_F16_2(S[1][0], qh1, bk[0], bk[1]);
        MMA_F16_2(S[0][1], qh0, bk[2], bk[3]);
        MMA_F16_2(S[1][1], qh1, bk[2], bk[3]);
    }
}

__global__ __launch_bounds__(128, 2) void attn_kernel() {
    extern __shared__ char smem[];
    const int tid = threadIdx.x;
    const int wid = tid >> 5, lane = tid & 31;
    const int qr = lane >> 2, qc = lane & 3;
    const int i0 = blockIdx.x * 128, h = blockIdx.y, b = blockIdx.z;
    const size_t bh = (size_t)b * HEADS + h;

    const uint32_t sb = smem_u32(smem);
    const uint32_t aOff = (uint32_t)((lane & 15) * RS + (lane >> 4) * 16);
    // B fragments (K and V): single plane; lanes 16-31 -> next n-tile (rows +8)
    const uint32_t nOff = (uint32_t)((lane >> 4) * (8 * RS) + ((lane >> 3) & 1) * 16 + (lane & 7) * RS);
    const uint32_t qBase = sb + (uint32_t)(wid * 32) * RS + aOff;

    const __half* kfp = g_kf + bh * N * DH;
    const __half* vfp = g_vf + bh * DH * N;

    // ---- stage Q plane into persistent smem region ----
    const __half* qfp = g_qf + (bh * N + i0) * DH;
    #pragma unroll
    for (int it = 0; it < 8; it++) {
        int idx = tid + it * 128;          // 1024 uint4
        int row = idx >> 3, ch = idx & 7;
        uint32_t so = (uint32_t)row * RS + ch * 16;
        *(uint4*)(smem + so) = *(const uint4*)(qfp + (size_t)row * DH + ch * 8);
    }

    float O[2][8][4] = {};
    float ls0[2] = {0.f, 0.f}, ls1[2] = {0.f, 0.f};

    for (int tile = 0; tile < 32; tile++) {
        const int j0 = tile * 64;
        char* bb = smem + 18432 + (tile & 1) * 18432;
        #pragma unroll
        for (int it = 0; it < 4; it++) {
            int idx = tid + it * 128;      // 512 uint4 per plane
            int row = idx >> 3, ch = idx & 7;
            uint32_t so = (uint32_t)row * RS + ch * 16;
            *(uint4*)(bb + so)        = *(const uint4*)(kfp + (size_t)(j0 + row) * DH + ch * 8);
            *(uint4*)(bb + 9216 + so) = *(const uint4*)(vfp + (size_t)row * N + j0 + ch * 8);
        }
        __syncthreads();   // also covers Q staging on tile 0

        const uint32_t base = sb + 18432u + (uint32_t)((tile & 1) * 18432);
        const uint32_t kB = base + nOff;
        const uint32_t vB = base + 9216u + nOff;

        float S[2][2][2][4];   // [parity][m][nn][4]
        qk_burst(S[0], kB, qBase);

        #pragma unroll
        for (int pr = 0; pr < 4; pr++) {
            const int cur = pr & 1;
            if (pr < 3)
                qk_burst(S[cur ^ 1], kB + (uint32_t)((pr + 1) * 16) * RS, qBase);

            // softmax(pr): max-free exp; P single fp16 plane
            uint32_t pa[2][4];
            #pragma unroll
            for (int m = 0; m < 2; m++)
                #pragma unroll
                for (int nn = 0; nn < 2; nn++) {
                    float p0 = __expf(S[cur][m][nn][0]), p1 = __expf(S[cur][m][nn][1]);
                    float p2 = __expf(S[cur][m][nn][2]), p3 = __expf(S[cur][m][nn][3]);
                    ls0[m] += p0 + p1;
                    ls1[m] += p2 + p3;
                    pa[m][nn * 2 + 0] = pack_f16(p0, p1);
                    pa[m][nn * 2 + 1] = pack_f16(p2, p3);
                }
            // PV(pr): O += P x V, single plane, 1 LDSM per nd-pair
            #pragma unroll
            for (int ndp = 0; ndp < 4; ndp++) {
                const int n0 = ndp * 2, n1 = ndp * 2 + 1;
                uint32_t bv[4];
                LDSM_X4(bv, vB + (uint32_t)ndp * (16 * RS) + pr * 32);
                MMA_F16_2(O[0][n0], pa[0], bv[0], bv[1]);
                MMA_F16_2(O[1][n0], pa[1], bv[0], bv[1]);
                MMA_F16_2(O[0][n1], pa[0], bv[2], bv[3]);
                MMA_F16_2(O[1][n1], pa[1], bv[2], bv[3]);
            }
        }
    }

    #pragma unroll
    for (int m = 0; m < 2; m++) {
        ls0[m] += __shfl_xor_sync(0xffffffffu, ls0[m], 1);
        ls0[m] += __shfl_xor_sync(0xffffffffu, ls0[m], 2);
        ls1[m] += __shfl_xor_sync(0xffffffffu, ls1[m], 1);
        ls1[m] += __shfl_xor_sync(0xffffffffu, ls1[m], 2);
    }

    // ---- epilogue: normalized bf16 hi/lo -> g_ah/g_al [b][t][c] ----
    #pragma unroll
    for (int m = 0; m < 2; m++) {
        const float inv0 = 1.f / ls0[m], inv1 = 1.f / ls1[m];
        size_t r0 = ((size_t)b * N + i0 + wid * 32 + m * 16 + qr) * HID + h * DH;
        size_t r1 = r0 + 8 * HID;
        #pragma unroll
        for (int nd = 0; nd < 8; nd++) {
            const int d = nd * 8 + qc * 2;
            float v0 = O[m][nd][0] * inv0, v1 = O[m][nd][1] * inv0;
            float v2 = O[m][nd][2] * inv1, v3 = O[m][nd][3] * inv1;
            float h0 = bf16_round(v0), h1 = bf16_round(v1);
            float h2 = bf16_round(v2), h3 = bf16_round(v3);
            *(uint32_t*)&g_ah[r0 + d] = pack_bf16(h0, h1);
            *(uint32_t*)&g_al[r0 + d] = pack_bf16(v0 - h0, v1 - h1);
            *(uint32_t*)&g_ah[r1 + d] = pack_bf16(h2, h3);
            *(uint32_t*)&g_al[r1 + d] = pack_bf16(v2 - h2, v3 - h3);
        }
    }
}

// ---------------------------------------------------------------------------
extern "C" void kernel_launch(void* const* d_in, const int* in_sizes, int n_in,
                              void* d_out, int out_size) {
    const float* x     = (const float*)d_in[0];
    const float* w_qkv = (const float*)d_in[1];
    const float* w_out = (const float*)d_in[2];
    const float* b_out = (const float*)d_in[3];
    float* out = (float*)d_out;

    cudaFuncSetAttribute(gemm_kernel<DIM, 0>,
                         cudaFuncAttributeMaxDynamicSharedMemorySize, SM_GEMM);
    cudaFuncSetAttribute(gemm_kernel<HID, 1>,
                         cudaFuncAttributeMaxDynamicSharedMemorySize, SM_GEMM);
    cudaFuncSetAttribute(attn_kernel,
                         cudaFuncAttributeMaxDynamicSharedMemorySize, SM_ATTN);

    split_w<<<(3 * HID * DIM + DIM * HID) / 256, 256>>>(w_qkv, w_out);
    split_x<<<dim3(N / 64, DIM / 64, B), 256>>>(x);
    gemm_kernel<DIM, 0><<<dim3(N / 64, 3 * HID / 128, B), 128, SM_GEMM>>>(nullptr, nullptr);
    attn_kernel<<<dim3(N / 128, HEADS, B), 128, SM_ATTN>>>();
    gemm_kernel<HID, 1><<<dim3(N / 64, DIM / 128, B), 128, SM_GEMM>>>(b_out, out);
}